// round 9
// baseline (speedup 1.0000x reference)
#include <cuda_runtime.h>
#include <cuda_fp16.h>

#define NROW 1024
#define HDIM 300
#define MID  100
#define NJ   1025
#define OUT_LD 1025
#define MPAD 104
#define S2P  1088
#define SCP  1088
#define NTILE 544        // 17 j-tiles x 32 i-tiles
#define S2HP 72          // k2 s2 tile pitch in halves (64 + 8 pad)

// ---- device scratch (zero-initialized at load; pads never written -> stay 0) ----
__device__ __align__(16) float g_s1[NROW * MPAD];
__device__ __align__(16) float g_s2T[MID * S2P];
__device__ __align__(16) float g_w2[MID];          // 0.5*w2
__device__ __align__(16) float g_scores[NROW * SCP]; // exp(score) scratch
__device__ float g_C[1];
__device__ float g_blockloss[NTILE];
__device__ unsigned g_done;

__device__ __forceinline__ __half2 tanh_h2(__half2 x) {
    unsigned r, xi = *reinterpret_cast<unsigned*>(&x);
    asm("tanh.approx.f16x2 %0, %1;" : "=r"(r) : "r"(xi));
    return *reinterpret_cast<__half2*>(&r);
}

// ================= k1: dual GEMM, register tile 2 rows x 7 m =================
// 64 compute blocks x 256 threads: block = 32 rows x 112 m (100 used).
// thread: tr = tid>>4 -> rows 2tr,2tr+1 ; mg = tid&15 -> m0 = mg*7.
#define HC 60
__global__ void __launch_bounds__(256) k1_gemm(const float* __restrict__ sent,
                                               const float* __restrict__ W1,
                                               const float* __restrict__ b1,
                                               const float* __restrict__ W2,
                                               const float* __restrict__ b2) {
    int b = blockIdx.x;
    int tid = threadIdx.x;

    if (b == 64) {   // prep
        if (tid < MID) {
            g_w2[tid] = 0.5f * W2[tid];
            g_s2T[tid * S2P + 0] = 0.5f * b1[tid];   // j=0: pm row is zeros
        }
        if (tid == 0) {
            float s = 0.f;
#pragma unroll
            for (int m = 0; m < MID; m++) s += W2[m];
            g_C[0] = b2[0] + 0.5f * s;
        }
        return;
    }

    __shared__ float4 rs4[32][17];      // 32 rows x 15 used h4
    __shared__ float4 ws4[112][17];     // 112 m x 15 used h4

    bool isS1 = (b < 32);
    int r0 = (b & 31) * 32;             // base row within the 1024-row half
    int woff = isS1 ? 0 : HDIM;
    const float* src = sent + (size_t)r0 * HDIM;

    int tr = tid >> 4;                  // 0..15 -> rows 2tr, 2tr+1
    int mg = tid & 15;                  // 0..15 -> m0 = mg*7 (0..105)
    int m0 = mg * 7;

    float acc[14];
#pragma unroll
    for (int c = 0; c < 14; c++) acc[c] = 0.f;

    for (int hc = 0; hc < HDIM; hc += HC) {
        // stage rows: 32 x 15 float4 = 480
        for (int q = tid; q < 32 * 15; q += 256) {
            int rr = q / 15, h4 = q % 15;
            rs4[rr][h4] = *(const float4*)(src + rr * HDIM + hc + h4 * 4);
        }
        // stage weights: 112 x 15 float4 (m>=100 zero)
        for (int q = tid; q < 112 * 15; q += 256) {
            int m = q / 15, h4 = q % 15;
            float4 v = make_float4(0.f, 0.f, 0.f, 0.f);
            if (m < MID) v = *(const float4*)(W1 + m * (2 * HDIM) + woff + hc + h4 * 4);
            ws4[m][h4] = v;
        }
        __syncthreads();
#pragma unroll
        for (int h4 = 0; h4 < 15; h4++) {
            float4 ra = rs4[2 * tr][h4];
            float4 rb = rs4[2 * tr + 1][h4];
#pragma unroll
            for (int c = 0; c < 7; c++) {
                float4 wv = ws4[m0 + c][h4];
                acc[c]     = fmaf(ra.x, wv.x, acc[c]);
                acc[c]     = fmaf(ra.y, wv.y, acc[c]);
                acc[c]     = fmaf(ra.z, wv.z, acc[c]);
                acc[c]     = fmaf(ra.w, wv.w, acc[c]);
                acc[7 + c] = fmaf(rb.x, wv.x, acc[7 + c]);
                acc[7 + c] = fmaf(rb.y, wv.y, acc[7 + c]);
                acc[7 + c] = fmaf(rb.z, wv.z, acc[7 + c]);
                acc[7 + c] = fmaf(rb.w, wv.w, acc[7 + c]);
            }
        }
        __syncthreads();
    }

    if (isS1) {
#pragma unroll
        for (int k = 0; k < 2; k++) {
            int i = r0 + 2 * tr + k;
#pragma unroll
            for (int c = 0; c < 7; c++) {
                int m = m0 + c;
                if (m < MID) g_s1[i * MPAD + m] = 0.5f * acc[7 * k + c];
            }
        }
    } else {
#pragma unroll
        for (int k = 0; k < 2; k++) {
            int j = r0 + 2 * tr + k + 1;   // 1..1024
#pragma unroll
            for (int c = 0; c < 7; c++) {
                int m = m0 + c;
                if (m < MID) g_s2T[m * S2P + j] = 0.5f * (acc[7 * k + c] + b1[m]);
            }
        }
    }
}

// ================= k2: pairwise scores (f16 add + f16x2 tanh, f32 accumulate) =================
// Tile 32i x 64j, 256 threads: thread = 1 i x 8 j. Also: exp(score) store + loss partial.
__global__ void __launch_bounds__(256) k2_scores(const int* __restrict__ tgt) {
    __shared__ float  s1t[32][MPAD];
    __shared__ __align__(16) __half s2h[MID * S2HP];   // [m][j] as f16
    __shared__ float  w2t[MID];
    __shared__ float  csh;
    __shared__ float  red[8];

    int tid = threadIdx.x;
    int i0 = blockIdx.y * 32;
    int j0 = blockIdx.x * 64;

    for (int q = tid; q < 32 * MPAD; q += 256)
        s1t[q / MPAD][q % MPAD] = g_s1[(i0 + q / MPAD) * MPAD + (q % MPAD)];
    for (int q = tid; q < MID * 16; q += 256) {
        int m = q >> 4, f4 = q & 15;
        float4 v = *(const float4*)(g_s2T + m * S2P + j0 + f4 * 4);
        __half2 h0 = __floats2half2_rn(v.x, v.y);
        __half2 h1 = __floats2half2_rn(v.z, v.w);
        *(__half2*)(s2h + m * S2HP + f4 * 4)     = h0;
        *(__half2*)(s2h + m * S2HP + f4 * 4 + 2) = h1;
    }
    if (tid < MID) w2t[tid] = g_w2[tid];
    if (tid == 0) csh = g_C[0];
    __syncthreads();

    int ti = tid >> 3;
    int tg = tid & 7;
    float acc[8];
#pragma unroll
    for (int c = 0; c < 8; c++) acc[c] = 0.f;

#pragma unroll 2
    for (int m = 0; m < MID; m++) {
        __half2 ah = __float2half2_rn(s1t[ti][m]);
        float w = w2t[m];
        uint4 pv = *(const uint4*)(s2h + m * S2HP + tg * 8);  // 8 halves
#pragma unroll
        for (int c = 0; c < 4; c++) {
            unsigned pu = (c == 0) ? pv.x : (c == 1) ? pv.y : (c == 2) ? pv.z : pv.w;
            __half2 p = *reinterpret_cast<__half2*>(&pu);
            __half2 t = tanh_h2(__hadd2(ah, p));
            acc[2 * c]     = fmaf(w, __low2float(t),  acc[2 * c]);
            acc[2 * c + 1] = fmaf(w, __high2float(t), acc[2 * c + 1]);
        }
    }

    float C = csh;
    int i = i0 + ti;
    int jbase = j0 + tg * 8;
    int tgv = tgt[i];
    float lossacc = 0.f;
    float e[8];
#pragma unroll
    for (int c = 0; c < 8; c++) {
        int j = jbase + c;
        float s = acc[c] + C;
        e[c] = __expf(s);
        if (j < NJ) lossacc += fabsf(s - ((j == tgv) ? 1.f : 0.f));
    }
    float* dst = g_scores + (size_t)i * SCP + jbase;
    *(float4*)dst       = make_float4(e[0], e[1], e[2], e[3]);
    *(float4*)(dst + 4) = make_float4(e[4], e[5], e[6], e[7]);

    // deterministic block loss reduce
#pragma unroll
    for (int off = 16; off > 0; off >>= 1)
        lossacc += __shfl_xor_sync(0xffffffffu, lossacc, off);
    if ((tid & 31) == 0) red[tid >> 5] = lossacc;
    __syncthreads();
    if (tid == 0) {
        float s = red[0];
#pragma unroll
        for (int w = 1; w < 8; w++) s += red[w];
        g_blockloss[blockIdx.y * 17 + blockIdx.x] = s;
    }
}

// ================= k3: row-sum + normalize; last block reduces loss =================
__global__ void __launch_bounds__(256) k3_softmax(float* __restrict__ out) {
    __shared__ float red[8];
    __shared__ bool amLast;
    int i = blockIdx.x, t = threadIdx.x;
    const float* row = g_scores + (size_t)i * SCP;
    float4 v = ((const float4*)row)[t];
    float extra = row[1024];
    float sum = v.x + v.y + v.z + v.w;
    if (t == 0) sum += extra;
#pragma unroll
    for (int off = 16; off > 0; off >>= 1)
        sum += __shfl_xor_sync(0xffffffffu, sum, off);
    if ((t & 31) == 0) red[t >> 5] = sum;
    __syncthreads();
    float tot = 0.f;
#pragma unroll
    for (int w = 0; w < 8; w++) tot += red[w];
    float inv = 1.0f / tot;
    float* o = out + 1 + (size_t)i * OUT_LD + 4 * t;
    o[0] = v.x * inv;
    o[1] = v.y * inv;
    o[2] = v.z * inv;
    o[3] = v.w * inv;
    if (t == 0) out[1 + (size_t)i * OUT_LD + 1024] = extra * inv;

    // ticket: last block computes the loss from k2's per-block partials
    if (t == 0) {
        __threadfence();
        amLast = (atomicAdd(&g_done, 1u) == NROW - 1);
    }
    __syncthreads();
    if (amLast) {
        float s = g_blockloss[t] + g_blockloss[t + 256];
        if (t < NTILE - 512) s += g_blockloss[t + 512];
#pragma unroll
        for (int off = 16; off > 0; off >>= 1)
            s += __shfl_xor_sync(0xffffffffu, s, off);
        if ((t & 31) == 0) red[t >> 5] = s;
        __syncthreads();
        if (t == 0) {
            float tl = 0.f;
#pragma unroll
            for (int w = 0; w < 8; w++) tl += red[w];
            out[0] = tl * (1.0f / (1024.0f * 1025.0f));
            g_done = 0;   // replay-safe reset
        }
    }
}

extern "C" void kernel_launch(void* const* d_in, const int* in_sizes, int n_in,
                              void* d_out, int out_size) {
    const float* sentence;
    const int*   tgt;
    const float* W1;
    const float* b1;
    const float* W2;
    const float* b2;

    if (n_in >= 6 && in_sizes[1] == 1024) {
        sentence = (const float*)d_in[0];
        tgt      = (const int*)d_in[1];
        W1       = (const float*)d_in[2];
        b1       = (const float*)d_in[3];
        W2       = (const float*)d_in[4];
        b2       = (const float*)d_in[5];
    } else {
        sentence = (const float*)d_in[0];
        W1       = (const float*)d_in[1];
        b1       = (const float*)d_in[2];
        W2       = (const float*)d_in[3];
        b2       = (const float*)d_in[4];
        tgt      = (const int*)d_in[5];
    }

    float* out = (float*)d_out;

    k1_gemm<<<65, 256>>>(sentence, W1, b1, W2, b2);
    dim3 g2(17, 32);
    k2_scores<<<g2, 256>>>(tgt);
    k3_softmax<<<1024, 256>>>(out);
}

// round 12
// speedup vs baseline: 1.7660x; 1.7660x over previous
#include <cuda_runtime.h>
#include <cuda_fp16.h>

#define NROW 1024
#define HDIM 300
#define MID  100
#define NJ   1025
#define OUT_LD 1025
#define MPAD 104
#define S2P  1088
#define SCP  1088
#define NTILE 544        // 17 j-tiles x 32 i-tiles
#define S2HP 72          // k2 s2 tile pitch in halves (64 + 8 pad)
#define KSPLIT 5
#define HC 60            // h per split chunk (5*60 = 300)
#define PPITCH 112       // partial pitch in floats

// ---- device scratch (zero-initialized at load; pads never written -> stay 0) ----
__device__ __align__(16) float g_part[KSPLIT * 2048 * PPITCH];  // raw GEMM partials
__device__ __align__(16) float g_s1[NROW * MPAD];
__device__ __align__(16) float g_s2T[MID * S2P];
__device__ __align__(16) float g_w2[MID];          // 0.5*w2
__device__ __align__(16) float g_scores[NROW * SCP]; // exp(score) scratch
__device__ float g_C[1];
__device__ float g_blockloss[NTILE];
__device__ unsigned g_done;

__device__ __forceinline__ __half2 tanh_h2(__half2 x) {
    unsigned r, xi = *reinterpret_cast<unsigned*>(&x);
    asm("tanh.approx.f16x2 %0, %1;" : "=r"(r) : "r"(xi));
    return *reinterpret_cast<__half2*>(&r);
}

// ================= k1: split-K dual GEMM =================
// grid (128, 5): blockIdx.x = row-block (16 virtual rows), blockIdx.y = h-chunk.
// 256 threads: r = tid&15 (row), mg = tid>>4 (m = mg + 16c, c<7).
// smem transposed to [h4][...] so inner LDS.128 are contiguous across threads.
__global__ void __launch_bounds__(256) k1_gemm(const float* __restrict__ sent,
                                               const float* __restrict__ W1) {
    __shared__ float4 rsI[15][17];      // [h4][row]  (16 rows used)
    __shared__ float4 wsI[15][113];     // [h4][m]    (112 m slots, 100 used)

    int b  = blockIdx.x;               // 0..127
    int kc = blockIdx.y;               // 0..4
    int tid = threadIdx.x;

    bool isS1 = (b < 64);
    int r0 = (b & 63) * 16;
    int woff = (isS1 ? 0 : HDIM) + kc * HC;
    const float* src = sent + (size_t)r0 * HDIM + kc * HC;

    // stage rows: 16 x 15 float4 (coalesced LDG, transposed STS)
    if (tid < 240) {
        int rr = tid / 15, h4 = tid % 15;
        rsI[h4][rr] = *(const float4*)(src + rr * HDIM + h4 * 4);
    }
    // stage weights: 112 x 15 float4 (m >= 100 zero)
    for (int q = tid; q < 112 * 15; q += 256) {
        int m = q / 15, h4 = q % 15;
        float4 v = make_float4(0.f, 0.f, 0.f, 0.f);
        if (m < MID) v = *(const float4*)(W1 + m * (2 * HDIM) + woff + h4 * 4);
        wsI[h4][m] = v;
    }
    __syncthreads();

    int r  = tid & 15;
    int mg = tid >> 4;

    float acc[7];
#pragma unroll
    for (int c = 0; c < 7; c++) acc[c] = 0.f;

#pragma unroll
    for (int h4 = 0; h4 < 15; h4++) {
        float4 ra = rsI[h4][r];
#pragma unroll
        for (int c = 0; c < 7; c++) {
            float4 wv = wsI[h4][mg + 16 * c];
            acc[c] = fmaf(ra.x, wv.x, acc[c]);
            acc[c] = fmaf(ra.y, wv.y, acc[c]);
            acc[c] = fmaf(ra.z, wv.z, acc[c]);
            acc[c] = fmaf(ra.w, wv.w, acc[c]);
        }
    }

    int vr = b * 16 + r;   // 0..2047 (b<64: s1 rows; b>=64: s2 rows)
    float* dst = g_part + ((size_t)kc * 2048 + vr) * PPITCH;
#pragma unroll
    for (int c = 0; c < 7; c++) {
        int m = mg + 16 * c;
        if (m < MID) dst[m] = acc[c];
    }
}

// ================= k1b: reduce split-K partials + prep =================
// 800 compute blocks x 256 threads = 204800 = 2048*100 outputs; block 800 = prep.
__global__ void __launch_bounds__(256) k1b_reduce(const float* __restrict__ b1,
                                                  const float* __restrict__ W2,
                                                  const float* __restrict__ b2) {
    int tid = threadIdx.x;
    if (blockIdx.x == 800) {   // prep
        if (tid < MID) {
            g_w2[tid] = 0.5f * W2[tid];
            g_s2T[tid * S2P + 0] = 0.5f * b1[tid];   // j=0: pm row is zeros
        }
        if (tid == 0) {
            float s = 0.f;
#pragma unroll
            for (int m = 0; m < MID; m++) s += W2[m];
            g_C[0] = b2[0] + 0.5f * s;
        }
        return;
    }
    int gid = blockIdx.x * 256 + tid;
    int vr = gid / MID;
    int m  = gid - vr * MID;
    float s = 0.f;
#pragma unroll
    for (int k = 0; k < KSPLIT; k++)
        s += g_part[((size_t)k * 2048 + vr) * PPITCH + m];
    if (vr < NROW) {
        g_s1[vr * MPAD + m] = 0.5f * s;
    } else {
        int j = vr - 1023;   // 1..1024
        g_s2T[m * S2P + j] = 0.5f * (s + b1[m]);
    }
}

// ================= k2: pairwise scores (f16 add + f16x2 tanh, f32 accumulate) =================
// Tile 32i x 64j, 256 threads: thread = 1 i x 8 j. Also: exp(score) store + loss partial.
__global__ void __launch_bounds__(256) k2_scores(const int* __restrict__ tgt) {
    __shared__ float  s1t[32][MPAD];
    __shared__ __align__(16) __half s2h[MID * S2HP];   // [m][j] as f16
    __shared__ float  w2t[MID];
    __shared__ float  csh;
    __shared__ float  red[8];

    int tid = threadIdx.x;
    int i0 = blockIdx.y * 32;
    int j0 = blockIdx.x * 64;

    for (int q = tid; q < 32 * MPAD; q += 256)
        s1t[q / MPAD][q % MPAD] = g_s1[(i0 + q / MPAD) * MPAD + (q % MPAD)];
    for (int q = tid; q < MID * 16; q += 256) {
        int m = q >> 4, f4 = q & 15;
        float4 v = *(const float4*)(g_s2T + m * S2P + j0 + f4 * 4);
        __half2 h0 = __floats2half2_rn(v.x, v.y);
        __half2 h1 = __floats2half2_rn(v.z, v.w);
        *(__half2*)(s2h + m * S2HP + f4 * 4)     = h0;
        *(__half2*)(s2h + m * S2HP + f4 * 4 + 2) = h1;
    }
    if (tid < MID) w2t[tid] = g_w2[tid];
    if (tid == 0) csh = g_C[0];
    __syncthreads();

    int ti = tid >> 3;
    int tg = tid & 7;
    float acc[8];
#pragma unroll
    for (int c = 0; c < 8; c++) acc[c] = 0.f;

#pragma unroll 2
    for (int m = 0; m < MID; m++) {
        __half2 ah = __float2half2_rn(s1t[ti][m]);
        float w = w2t[m];
        uint4 pv = *(const uint4*)(s2h + m * S2HP + tg * 8);  // 8 halves
#pragma unroll
        for (int c = 0; c < 4; c++) {
            unsigned pu = (c == 0) ? pv.x : (c == 1) ? pv.y : (c == 2) ? pv.z : pv.w;
            __half2 p = *reinterpret_cast<__half2*>(&pu);
            __half2 t = tanh_h2(__hadd2(ah, p));
            acc[2 * c]     = fmaf(w, __low2float(t),  acc[2 * c]);
            acc[2 * c + 1] = fmaf(w, __high2float(t), acc[2 * c + 1]);
        }
    }

    float C = csh;
    int i = i0 + ti;
    int jbase = j0 + tg * 8;
    int tgv = tgt[i];
    float lossacc = 0.f;
    float e[8];
#pragma unroll
    for (int c = 0; c < 8; c++) {
        int j = jbase + c;
        float s = acc[c] + C;
        e[c] = __expf(s);
        if (j < NJ) lossacc += fabsf(s - ((j == tgv) ? 1.f : 0.f));
    }
    float* dst = g_scores + (size_t)i * SCP + jbase;
    *(float4*)dst       = make_float4(e[0], e[1], e[2], e[3]);
    *(float4*)(dst + 4) = make_float4(e[4], e[5], e[6], e[7]);

    // deterministic block loss reduce
#pragma unroll
    for (int off = 16; off > 0; off >>= 1)
        lossacc += __shfl_xor_sync(0xffffffffu, lossacc, off);
    if ((tid & 31) == 0) red[tid >> 5] = lossacc;
    __syncthreads();
    if (tid == 0) {
        float s = red[0];
#pragma unroll
        for (int w = 1; w < 8; w++) s += red[w];
        g_blockloss[blockIdx.y * 17 + blockIdx.x] = s;
    }
}

// ================= k3: row-sum + normalize; last block reduces loss =================
__global__ void __launch_bounds__(256) k3_softmax(float* __restrict__ out) {
    __shared__ float red[8];
    __shared__ bool amLast;
    int i = blockIdx.x, t = threadIdx.x;
    const float* row = g_scores + (size_t)i * SCP;
    float4 v = ((const float4*)row)[t];
    float extra = row[1024];
    float sum = v.x + v.y + v.z + v.w;
    if (t == 0) sum += extra;
#pragma unroll
    for (int off = 16; off > 0; off >>= 1)
        sum += __shfl_xor_sync(0xffffffffu, sum, off);
    if ((t & 31) == 0) red[t >> 5] = sum;
    __syncthreads();
    float tot = 0.f;
#pragma unroll
    for (int w = 0; w < 8; w++) tot += red[w];
    float inv = 1.0f / tot;
    float* o = out + 1 + (size_t)i * OUT_LD + 4 * t;
    o[0] = v.x * inv;
    o[1] = v.y * inv;
    o[2] = v.z * inv;
    o[3] = v.w * inv;
    if (t == 0) out[1 + (size_t)i * OUT_LD + 1024] = extra * inv;

    // ticket: last block computes the loss from k2's per-block partials
    if (t == 0) {
        __threadfence();
        amLast = (atomicAdd(&g_done, 1u) == NROW - 1);
    }
    __syncthreads();
    if (amLast) {
        float s = g_blockloss[t] + g_blockloss[t + 256];
        if (t < NTILE - 512) s += g_blockloss[t + 512];
#pragma unroll
        for (int off = 16; off > 0; off >>= 1)
            s += __shfl_xor_sync(0xffffffffu, s, off);
        if ((t & 31) == 0) red[t >> 5] = s;
        __syncthreads();
        if (t == 0) {
            float tl = 0.f;
#pragma unroll
            for (int w = 0; w < 8; w++) tl += red[w];
            out[0] = tl * (1.0f / (1024.0f * 1025.0f));
            g_done = 0;   // replay-safe reset
        }
    }
}

extern "C" void kernel_launch(void* const* d_in, const int* in_sizes, int n_in,
                              void* d_out, int out_size) {
    const float* sentence;
    const int*   tgt;
    const float* W1;
    const float* b1;
    const float* W2;
    const float* b2;

    if (n_in >= 6 && in_sizes[1] == 1024) {
        sentence = (const float*)d_in[0];
        tgt      = (const int*)d_in[1];
        W1       = (const float*)d_in[2];
        b1       = (const float*)d_in[3];
        W2       = (const float*)d_in[4];
        b2       = (const float*)d_in[5];
    } else {
        sentence = (const float*)d_in[0];
        W1       = (const float*)d_in[1];
        b1       = (const float*)d_in[2];
        W2       = (const float*)d_in[3];
        b2       = (const float*)d_in[4];
        tgt      = (const int*)d_in[5];
    }

    float* out = (float*)d_out;

    dim3 g1(128, KSPLIT);
    k1_gemm<<<g1, 256>>>(sentence, W1);
    k1b_reduce<<<801, 256>>>(b1, W2, b2);
    dim3 g2(17, 32);
    k2_scores<<<g2, 256>>>(tgt);
    k3_softmax<<<1024, 256>>>(out);
}